// round 12
// baseline (speedup 1.0000x reference)
#include <cuda_runtime.h>
#include <cuda_bf16.h>
#include <cstdint>

// out[b,n,d] = x[b,n] * W[n,d] + bias[n,d]   B=128, N=1024, D=512 fp32
//
// Model (locked by R8-R10 evidence): steady-state wall == 268MB compulsory
// output drain @ ~6.1 TB/s ~= 44us. L2 pinning unavailable (no carveout,
// SetLimit forbidden; hints measured as placebo). Remaining lever: shape
// overhead. R11: best stream length (32 stores/thread) + 256-thread CTAs
// (4 neurons each) -> 1024 CTAs, fewer launch/exit events, near-single wave,
// STG.256 throughout.

static constexpr int B_ = 128;
static constexpr int N_ = 1024;
static constexpr int D4 = 512 / 4;            // 128 float4 per row
static constexpr int ND4 = N_ * D4;           // 131072 float4 per batch row
static constexpr int B_PER_BLK = 32;
static constexpr int N_PER_BLK = 4;           // neurons per CTA
static constexpr int THREADS = 256;           // 4 neurons x 64 chunks

__device__ __forceinline__ uint64_t pack2(float lo, float hi) {
    uint64_t q;
    asm("mov.b64 %0, {%1, %2};" : "=l"(q) : "r"(__float_as_uint(lo)), "r"(__float_as_uint(hi)));
    return q;
}

__device__ __forceinline__ void st256(float4* p, float4 a, float4 b) {
    asm volatile("st.global.v4.b64 [%0], {%1,%2,%3,%4};"
                 :: "l"(p), "l"(pack2(a.x, a.y)), "l"(pack2(a.z, a.w)),
                    "l"(pack2(b.x, b.y)), "l"(pack2(b.z, b.w)) : "memory");
}

__global__ __launch_bounds__(THREADS) void bcast_fma_st256_w_kernel(
    const float*  __restrict__ x,    // [B, N]
    const float4* __restrict__ W4,   // [N, D4]
    const float4* __restrict__ b4,   // [N, D4]
    float4*       __restrict__ out4) // [B, N, D4]
{
    const unsigned int tid     = threadIdx.x;       // 0..255
    const unsigned int n_local = tid >> 6;          // 0..3
    const unsigned int chunk   = tid & 63;          // 0..63 (32B chunks of a row)
    const unsigned int n       = blockIdx.x * N_PER_BLK + n_local;
    const unsigned int b0      = blockIdx.y * B_PER_BLK;
    const unsigned int nd4     = n * D4 + chunk * 2;   // float4 index, 32B aligned

    // Weights/bias for this 32B chunk: loaded once, reused 32x in registers.
    const float4 w0 = W4[nd4],     w1 = W4[nd4 + 1];
    const float4 c0 = b4[nd4],     c1 = b4[nd4 + 1];

    // Stage x scalars: xs[n_local][i] = x[b0+i, n]
    __shared__ float xs[N_PER_BLK][B_PER_BLK];
    if (tid < N_PER_BLK * B_PER_BLK) {
        unsigned int nl = tid >> 5, i = tid & 31;
        xs[nl][i] = x[(b0 + i) * N_ + blockIdx.x * N_PER_BLK + nl];
    }
    __syncthreads();

    unsigned int o_idx = b0 * ND4 + nd4;
    #pragma unroll 8
    for (int i = 0; i < B_PER_BLK; ++i) {
        const float s = xs[n_local][i];
        float4 o0, o1;
        o0.x = fmaf(s, w0.x, c0.x); o0.y = fmaf(s, w0.y, c0.y);
        o0.z = fmaf(s, w0.z, c0.z); o0.w = fmaf(s, w0.w, c0.w);
        o1.x = fmaf(s, w1.x, c1.x); o1.y = fmaf(s, w1.y, c1.y);
        o1.z = fmaf(s, w1.z, c1.z); o1.w = fmaf(s, w1.w, c1.w);
        st256(&out4[o_idx], o0, o1);
        o_idx += ND4;
    }
}

extern "C" void kernel_launch(void* const* d_in, const int* in_sizes, int n_in,
                              void* d_out, int out_size) {
    const float*  x  = (const float*)d_in[0];
    const float4* W4 = (const float4*)d_in[1];
    const float4* b4 = (const float4*)d_in[2];
    float4* out4 = (float4*)d_out;

    dim3 grid(N_ / N_PER_BLK, B_ / B_PER_BLK);   // 256 x 4 = 1024 blocks
    bcast_fma_st256_w_kernel<<<grid, THREADS>>>(x, W4, b4, out4);
}

// round 14
// speedup vs baseline: 1.0478x; 1.0478x over previous
#include <cuda_runtime.h>
#include <cuda_bf16.h>
#include <cstdint>

// out[b,n,d] = x[b,n] * W[n,d] + bias[n,d]   B=128, N=1024, D=512 fp32
//
// Shape sweep conclusion (R1-R12): optimum = 4096 CTAs x 128 threads,
// 16 x STG.256 per thread (R10: wall 44.1us, kernel 41.5us — the HBM
// write-drain floor is ~44us for 268MB compulsory output). R13 = R10 champion
// + prologue tweak: drop smem staging + __syncthreads; x-scalars are loaded
// directly (warp-uniform broadcast, L1-hit), so each CTA's first store
// issues one memory-latency earlier.

static constexpr int B_ = 128;
static constexpr int N_ = 1024;
static constexpr int D4 = 512 / 4;            // 128 float4 per row
static constexpr int ND4 = N_ * D4;           // 131072 float4 per batch row
static constexpr int B_PER_BLK = 16;

__device__ __forceinline__ uint64_t pack2(float lo, float hi) {
    uint64_t q;
    asm("mov.b64 %0, {%1, %2};" : "=l"(q) : "r"(__float_as_uint(lo)), "r"(__float_as_uint(hi)));
    return q;
}

__device__ __forceinline__ void st256(float4* p, float4 a, float4 b) {
    asm volatile("st.global.v4.b64 [%0], {%1,%2,%3,%4};"
                 :: "l"(p), "l"(pack2(a.x, a.y)), "l"(pack2(a.z, a.w)),
                    "l"(pack2(b.x, b.y)), "l"(pack2(b.z, b.w)) : "memory");
}

__global__ __launch_bounds__(128) void bcast_fma_st256_kernel(
    const float*  __restrict__ x,    // [B, N]
    const float4* __restrict__ W4,   // [N, D4]
    const float4* __restrict__ b4,   // [N, D4]
    float4*       __restrict__ out4) // [B, N, D4]
{
    const unsigned int tid     = threadIdx.x;       // 0..127
    const unsigned int n_local = tid >> 6;          // 0..1
    const unsigned int chunk   = tid & 63;          // 0..63 (32B chunks of a row)
    const unsigned int n       = blockIdx.x * 2 + n_local;
    const unsigned int b0      = blockIdx.y * B_PER_BLK;
    const unsigned int nd4     = n * D4 + chunk * 2;   // float4 index, 32B aligned

    // Weights/bias for this 32B chunk: loaded once, reused 16x in registers.
    const float4 w0 = W4[nd4],     w1 = W4[nd4 + 1];
    const float4 c0 = b4[nd4],     c1 = b4[nd4 + 1];

    // x scalars: warp-uniform broadcast loads (same address across the
    // 64 threads of a neuron-half); L1-resident after first touch.
    const float* xp = &x[b0 * N_ + n];

    unsigned int o_idx = b0 * ND4 + nd4;
    #pragma unroll
    for (int i = 0; i < B_PER_BLK; ++i) {
        const float s = __ldg(xp + i * N_);
        float4 o0, o1;
        o0.x = fmaf(s, w0.x, c0.x); o0.y = fmaf(s, w0.y, c0.y);
        o0.z = fmaf(s, w0.z, c0.z); o0.w = fmaf(s, w0.w, c0.w);
        o1.x = fmaf(s, w1.x, c1.x); o1.y = fmaf(s, w1.y, c1.y);
        o1.z = fmaf(s, w1.z, c1.z); o1.w = fmaf(s, w1.w, c1.w);
        st256(&out4[o_idx], o0, o1);
        o_idx += ND4;
    }
}

extern "C" void kernel_launch(void* const* d_in, const int* in_sizes, int n_in,
                              void* d_out, int out_size) {
    const float*  x  = (const float*)d_in[0];
    const float4* W4 = (const float4*)d_in[1];
    const float4* b4 = (const float4*)d_in[2];
    float4* out4 = (float4*)d_out;

    dim3 grid(N_ / 2, B_ / B_PER_BLK);   // 512 x 8 = 4096 blocks, 2 neurons/block
    bcast_fma_st256_kernel<<<grid, 128>>>(x, W4, b4, out4);
}

// round 15
// speedup vs baseline: 1.0612x; 1.0128x over previous
#include <cuda_runtime.h>
#include <cuda_bf16.h>
#include <cstdint>

// out[b,n,d] = x[b,n] * W[n,d] + bias[n,d]   B=128, N=1024, D=512 fp32
//
// FINAL (champion = R10, reproduced). Sweep evidence (wall us):
//   CTAs: 65536->58.1 | 8192->60.1 | 4096->44.1 | 2048->45.1 | 1024(256t)->47.7
//   -smem staging -> 45.5 | L2 evict hints -> 45.8 | __stcs -> regression
// Governing bound: 268MB compulsory fp32 output drained @ ~6.1 TB/s ~= 44us.
// Shape: 4096 CTAs x 128 threads; per thread: load W/b 32B chunk once,
// stage 16 x-scalars in smem, emit 16 independent STG.256.

static constexpr int B_ = 128;
static constexpr int N_ = 1024;
static constexpr int D4 = 512 / 4;            // 128 float4 per row
static constexpr int ND4 = N_ * D4;           // 131072 float4 per batch row
static constexpr int B_PER_BLK = 16;

__device__ __forceinline__ uint64_t pack2(float lo, float hi) {
    uint64_t q;
    asm("mov.b64 %0, {%1, %2};" : "=l"(q) : "r"(__float_as_uint(lo)), "r"(__float_as_uint(hi)));
    return q;
}

__device__ __forceinline__ void st256(float4* p, float4 a, float4 b) {
    asm volatile("st.global.v4.b64 [%0], {%1,%2,%3,%4};"
                 :: "l"(p), "l"(pack2(a.x, a.y)), "l"(pack2(a.z, a.w)),
                    "l"(pack2(b.x, b.y)), "l"(pack2(b.z, b.w)) : "memory");
}

__global__ __launch_bounds__(128) void bcast_fma_st256_kernel(
    const float*  __restrict__ x,    // [B, N]
    const float4* __restrict__ W4,   // [N, D4]
    const float4* __restrict__ b4,   // [N, D4]
    float4*       __restrict__ out4) // [B, N, D4]
{
    const unsigned int tid     = threadIdx.x;       // 0..127
    const unsigned int n_local = tid >> 6;          // 0..1
    const unsigned int chunk   = tid & 63;          // 0..63 (32B chunks of a row)
    const unsigned int n       = blockIdx.x * 2 + n_local;
    const unsigned int b0      = blockIdx.y * B_PER_BLK;
    const unsigned int nd4     = n * D4 + chunk * 2;   // float4 index, 32B aligned

    // Weights/bias for this 32B chunk: loaded once, reused 16x in registers.
    const float4 w0 = W4[nd4],     w1 = W4[nd4 + 1];
    const float4 c0 = b4[nd4],     c1 = b4[nd4 + 1];

    // Stage x scalars: xs[n_local][i] = x[b0+i, n]
    __shared__ float xs[2][B_PER_BLK];
    if (tid < 2 * B_PER_BLK) {
        unsigned int nl = tid >> 4, i = tid & 15;
        xs[nl][i] = x[(b0 + i) * N_ + blockIdx.x * 2 + nl];
    }
    __syncthreads();

    unsigned int o_idx = b0 * ND4 + nd4;
    #pragma unroll
    for (int i = 0; i < B_PER_BLK; ++i) {
        const float s = xs[n_local][i];
        float4 o0, o1;
        o0.x = fmaf(s, w0.x, c0.x); o0.y = fmaf(s, w0.y, c0.y);
        o0.z = fmaf(s, w0.z, c0.z); o0.w = fmaf(s, w0.w, c0.w);
        o1.x = fmaf(s, w1.x, c1.x); o1.y = fmaf(s, w1.y, c1.y);
        o1.z = fmaf(s, w1.z, c1.z); o1.w = fmaf(s, w1.w, c1.w);
        st256(&out4[o_idx], o0, o1);
        o_idx += ND4;
    }
}

extern "C" void kernel_launch(void* const* d_in, const int* in_sizes, int n_in,
                              void* d_out, int out_size) {
    const float*  x  = (const float*)d_in[0];
    const float4* W4 = (const float4*)d_in[1];
    const float4* b4 = (const float4*)d_in[2];
    float4* out4 = (float4*)d_out;

    dim3 grid(N_ / 2, B_ / B_PER_BLK);   // 512 x 8 = 4096 blocks, 2 neurons/block
    bcast_fma_st256_kernel<<<grid, 128>>>(x, W4, b4, out4);
}